// round 6
// baseline (speedup 1.0000x reference)
#include <cuda_runtime.h>
#include <cuda_bf16.h>
#include <cstdint>

#define B_   2
#define S_   2048
#define H_   1024
#define NH_  16
#define D_   64
#define MBS  (B_ * S_)

#define OUT_ELEMS  ((size_t)B_ * S_ * H_)
#define ATTN_ELEMS ((size_t)B_ * NH_ * S_ * S_)

// Scratch (device globals — no allocations allowed).
__device__ float g_q[OUT_ELEMS];
__device__ float g_k[OUT_ELEMS];
__device__ float g_v[OUT_ELEMS];
__device__ float g_ctx[OUT_ELEMS];
__device__ float g_attn_fallback[ATTN_ELEMS];

#define SMEM_SWIZZLE_128B(b) ((b) ^ (((b) >> 3) & 0x70))

// Smem: 2 buffers x (Ahi, Alo, Bhi, Blo) tiles of 16KB (128 rows x 128B).
#define T_AHI(buf) ((buf) * 65536 + 0)
#define T_ALO(buf) ((buf) * 65536 + 16384)
#define T_BHI(buf) ((buf) * 65536 + 32768)
#define T_BLO(buf) ((buf) * 65536 + 49152)
#define SMEM_BYTES 131072

__device__ __forceinline__ uint32_t smem_u32(const void* p) {
    uint32_t a;
    asm("{ .reg .u64 t; cvta.to.shared.u64 t, %1; cvt.u32.u64 %0, t; }"
        : "=r"(a) : "l"(p));
    return a;
}

__device__ __forceinline__ void ldsm_x4(uint32_t addr, uint32_t r[4]) {
    asm volatile("ldmatrix.sync.aligned.m8n8.x4.shared.b16 {%0,%1,%2,%3}, [%4];"
                 : "=r"(r[0]), "=r"(r[1]), "=r"(r[2]), "=r"(r[3]) : "r"(addr));
}

__device__ __forceinline__ void mma16816(float d[4], const uint32_t a[4],
                                         const uint32_t b[2]) {
    asm volatile(
        "mma.sync.aligned.m16n8k16.row.col.f32.bf16.bf16.f32 "
        "{%0,%1,%2,%3}, {%4,%5,%6,%7}, {%8,%9}, {%0,%1,%2,%3};"
        : "+f"(d[0]), "+f"(d[1]), "+f"(d[2]), "+f"(d[3])
        : "r"(a[0]), "r"(a[1]), "r"(a[2]), "r"(a[3]), "r"(b[0]), "r"(b[1]));
}

// f32 pair -> packed bf16x2 hi + bf16x2 lo (3-term split precision)
__device__ __forceinline__ void cv_pair(float x0, float x1,
                                        uint32_t& ph, uint32_t& pl) {
    __nv_bfloat16 h0 = __float2bfloat16(x0);
    __nv_bfloat16 h1 = __float2bfloat16(x1);
    __nv_bfloat16 l0 = __float2bfloat16(x0 - __bfloat162float(h0));
    __nv_bfloat16 l1 = __float2bfloat16(x1 - __bfloat162float(h1));
    ph = (uint32_t)__bfloat16_as_ushort(h0) | ((uint32_t)__bfloat16_as_ushort(h1) << 16);
    pl = (uint32_t)__bfloat16_as_ushort(l0) | ((uint32_t)__bfloat16_as_ushort(l1) << 16);
}

// ---------------------------------------------------------------------------
// Loaders: LDG (prefetch to regs) + STS (convert + store) halves.
// Tile layout: smem row = output row index (m or n), 64 bf16 k = 128B rows,
// swizzled by SMEM_SWIZZLE_128B.
// ---------------------------------------------------------------------------
__device__ __forceinline__ void ldg_kcontig(const float* __restrict__ base,
                                            size_t ld, int tid, float4 pa[8]) {
    const int row = tid >> 1, kb = (tid & 1) * 32;
    const float* src = base + (size_t)row * ld + kb;
#pragma unroll
    for (int j = 0; j < 8; j++) pa[j] = *(const float4*)(src + j * 4);
}

// FIXED (R5 NaN bug): per-j stride is 8 bytes (4 bf16 k-values -> h0 @ +0,
// h1 @ +4), previously j*16 which skipped bytes and overran the tile.
__device__ __forceinline__ void sts_kcontig(const float4 pa[8], char* smem,
                                            int tid, int hi, int lo) {
    const int row = tid >> 1, kb = (tid & 1) * 32;
    char* shi = smem + hi;
    char* slo = smem + lo;
#pragma unroll
    for (int j = 0; j < 8; j++) {
        uint32_t h0, l0, h1, l1;
        cv_pair(pa[j].x, pa[j].y, h0, l0);
        cv_pair(pa[j].z, pa[j].w, h1, l1);
        uint32_t b0 = SMEM_SWIZZLE_128B(row * 128 + kb * 2 + j * 8);
        *(uint32_t*)(shi + b0)     = h0;
        *(uint32_t*)(shi + b0 + 4) = h1;
        *(uint32_t*)(slo + b0)     = l0;
        *(uint32_t*)(slo + b0 + 4) = l1;
    }
}

// proj W: B tile row c (output col), content k=h: W[(c>>6)*H*D + h*64 + (c&63)]
__device__ __forceinline__ void ldg_projW(const float* __restrict__ W,
                                          int n0, int k0, int tid, float pb[32]) {
#pragma unroll
    for (int j = 0; j < 16; j++) {
        int idx = j * 256 + tid;
        int n   = idx & 127;
        int kk  = (idx >> 7) * 2;
        int ng  = n0 + n;
        const float* src = W + ((size_t)(ng >> 6) << 16)
                             + (size_t)(k0 + kk) * 64 + (ng & 63);
        pb[2 * j]     = src[0];
        pb[2 * j + 1] = src[64];
    }
}

__device__ __forceinline__ void sts_projW(const float pb[32], char* smem,
                                          int tid, int hi, int lo) {
    char* shi = smem + hi;
    char* slo = smem + lo;
#pragma unroll
    for (int j = 0; j < 16; j++) {
        int idx = j * 256 + tid;
        int n   = idx & 127;
        int kk  = (idx >> 7) * 2;
        uint32_t h, l;
        cv_pair(pb[2 * j], pb[2 * j + 1], h, l);
        uint32_t b = SMEM_SWIZZLE_128B(n * 128 + kk * 2);
        *(uint32_t*)(shi + b) = h;
        *(uint32_t*)(slo + b) = l;
    }
}

// K-strided B: element (n, k) = base[k*strideK + n], NR rows.
template <int NR>
__device__ __forceinline__ void ldg_kstrided(const float* __restrict__ base,
                                             size_t sK, int tid, float pb[]) {
#pragma unroll
    for (int j = 0; j < NR / 8; j++) {
        int idx = j * 256 + tid;
        int n   = idx & (NR - 1);
        int kk  = (idx / NR) * 2;
        pb[2 * j]     = base[(size_t)kk * sK + n];
        pb[2 * j + 1] = base[(size_t)(kk + 1) * sK + n];
    }
}

template <int NR>
__device__ __forceinline__ void sts_kstrided(const float pb[], char* smem,
                                             int tid, int hi, int lo) {
    char* shi = smem + hi;
    char* slo = smem + lo;
#pragma unroll
    for (int j = 0; j < NR / 8; j++) {
        int idx = j * 256 + tid;
        int n   = idx & (NR - 1);
        int kk  = (idx / NR) * 2;
        uint32_t h, l;
        cv_pair(pb[2 * j], pb[2 * j + 1], h, l);
        uint32_t b = SMEM_SWIZZLE_128B(n * 128 + kk * 2);
        *(uint32_t*)(shi + b) = h;
        *(uint32_t*)(slo + b) = l;
    }
}

// ---------------------------------------------------------------------------
// Warp-MMA compute over one BK=64 buffer. Warp tile = MT m16-tiles x 4 n8-tiles.
// 3-term bf16 split: hh + hl + lh into fp32 acc.
// ---------------------------------------------------------------------------
template <int MT>
__device__ __forceinline__ void compute_buf(uint32_t sAhi, uint32_t sAlo,
                                            uint32_t sBhi, uint32_t sBlo,
                                            int wmr, int wnc, int lane,
                                            float (&acc)[MT][4][4]) {
    const int j = lane >> 3, r = lane & 7;
    const int arow = ((j & 1) << 3) + r, aoff = (j >> 1) << 4;
    const int brow = ((j >> 1) << 3) + r, boff = (j & 1) << 4;
    const int xr = r << 4;
#pragma unroll
    for (int kk = 0; kk < 4; kk++) {
        uint32_t ah[MT][4], al[MT][4];
#pragma unroll
        for (int mt = 0; mt < MT; mt++) {
            uint32_t off = (uint32_t)((wmr + mt * 16 + arow) * 128
                                      + (((kk << 5) + aoff) ^ xr));
            ldsm_x4(sAhi + off, ah[mt]);
            ldsm_x4(sAlo + off, al[mt]);
        }
        uint32_t bh[2][4], bl[2][4];
#pragma unroll
        for (int g = 0; g < 2; g++) {
            uint32_t off = (uint32_t)((wnc + g * 16 + brow) * 128
                                      + (((kk << 5) + boff) ^ xr));
            ldsm_x4(sBhi + off, bh[g]);
            ldsm_x4(sBlo + off, bl[g]);
        }
#pragma unroll
        for (int mt = 0; mt < MT; mt++)
#pragma unroll
            for (int nt = 0; nt < 4; nt++) {
                const uint32_t* bhp = &bh[nt >> 1][(nt & 1) * 2];
                const uint32_t* blp = &bl[nt >> 1][(nt & 1) * 2];
                mma16816(acc[mt][nt], ah[mt], bhp);
                mma16816(acc[mt][nt], ah[mt], blp);
                mma16816(acc[mt][nt], al[mt], bhp);
            }
    }
}

template <int MT>
__device__ __forceinline__ void store_acc(float* C, size_t ldc, float scale,
                                          int wmr, int wnc, int lane,
                                          const float (&acc)[MT][4][4]) {
    const int rr = lane >> 2, cc = (lane & 3) * 2;
#pragma unroll
    for (int mt = 0; mt < MT; mt++)
#pragma unroll
        for (int nt = 0; nt < 4; nt++) {
            float* p0 = C + (size_t)(wmr + mt * 16 + rr) * ldc + wnc + nt * 8 + cc;
            *(float2*)p0 = make_float2(acc[mt][nt][0] * scale,
                                       acc[mt][nt][1] * scale);
            *(float2*)(p0 + 8 * ldc) = make_float2(acc[mt][nt][2] * scale,
                                                   acc[mt][nt][3] * scale);
        }
}

// ============================================================================
// Kernel 1: q/k/v projections. grid (H/128, MBS/128, 3). K=1024, 16 buffers.
// ============================================================================
__global__ __launch_bounds__(256, 1) void proj_mma(
    const float* __restrict__ inq, const float* __restrict__ ink,
    const float* __restrict__ inv,
    const float* __restrict__ Wq, const float* __restrict__ Wk,
    const float* __restrict__ Wv)
{
    extern __shared__ char smem[];
    const int z = blockIdx.z;
    const float* A = (z == 0) ? inq : (z == 1) ? ink : inv;
    const float* W = (z == 0) ? Wq  : (z == 1) ? Wk  : Wv;
    float* C       = (z == 0) ? g_q : (z == 1) ? g_k : g_v;

    const int tid = threadIdx.x, wid = tid >> 5, lane = tid & 31;
    const int m0 = blockIdx.y * 128, n0 = blockIdx.x * 128;
    const int wmr = (wid & 1) * 64, wnc = (wid >> 1) * 32;
    const uint32_t sb = smem_u32(smem);

    float acc[4][4][4];
#pragma unroll
    for (int a = 0; a < 4; a++)
#pragma unroll
        for (int b = 0; b < 4; b++)
#pragma unroll
            for (int c = 0; c < 4; c++) acc[a][b][c] = 0.f;

    float4 pa[8];
    float  pb[32];
    ldg_kcontig(A + (size_t)m0 * H_, H_, tid, pa);
    ldg_projW(W, n0, 0, tid, pb);
    sts_kcontig(pa, smem, tid, T_AHI(0), T_ALO(0));
    sts_projW(pb, smem, tid, T_BHI(0), T_BLO(0));
    __syncthreads();

    const int NIT = H_ / 64;
    for (int it = 0; it < NIT; it++) {
        const int cur = it & 1, nxt = cur ^ 1;
        if (it + 1 < NIT) {
            ldg_kcontig(A + (size_t)m0 * H_ + (it + 1) * 64, H_, tid, pa);
            ldg_projW(W, n0, (it + 1) * 64, tid, pb);
        }
        compute_buf<4>(sb + T_AHI(cur), sb + T_ALO(cur),
                       sb + T_BHI(cur), sb + T_BLO(cur), wmr, wnc, lane, acc);
        if (it + 1 < NIT) {
            sts_kcontig(pa, smem, tid, T_AHI(nxt), T_ALO(nxt));
            sts_projW(pb, smem, tid, T_BHI(nxt), T_BLO(nxt));
        }
        __syncthreads();
    }
    store_acc<4>(C + (size_t)m0 * H_ + n0, H_, 1.f, wmr, wnc, lane, acc);
}

// ============================================================================
// Kernel 2: scores = q k^T / 8. grid (S/128, S/128, B*NH). K=64, one buffer.
// ============================================================================
__global__ __launch_bounds__(256, 1) void scores_mma(float* __restrict__ attn)
{
    extern __shared__ char smem[];
    const int z = blockIdx.z, b = z >> 4, n = z & 15;
    const int tid = threadIdx.x, wid = tid >> 5, lane = tid & 31;
    const int m0 = blockIdx.y * 128, n0 = blockIdx.x * 128;
    const int wmr = (wid & 1) * 64, wnc = (wid >> 1) * 32;
    const uint32_t sb = smem_u32(smem);
    const float* qb = g_q + (size_t)b * S_ * H_ + n * D_;
    const float* kb = g_k + (size_t)b * S_ * H_ + n * D_;

    float acc[4][4][4];
#pragma unroll
    for (int a = 0; a < 4; a++)
#pragma unroll
        for (int c = 0; c < 4; c++)
#pragma unroll
            for (int d = 0; d < 4; d++) acc[a][c][d] = 0.f;

    float4 pa[8];
    ldg_kcontig(qb + (size_t)m0 * H_, H_, tid, pa);
    sts_kcontig(pa, smem, tid, T_AHI(0), T_ALO(0));
    ldg_kcontig(kb + (size_t)n0 * H_, H_, tid, pa);
    sts_kcontig(pa, smem, tid, T_BHI(0), T_BLO(0));
    __syncthreads();

    compute_buf<4>(sb + T_AHI(0), sb + T_ALO(0),
                   sb + T_BHI(0), sb + T_BLO(0), wmr, wnc, lane, acc);

    store_acc<4>(attn + (size_t)z * S_ * S_ + (size_t)m0 * S_ + n0,
                 S_, 0.125f, wmr, wnc, lane, acc);
}

// ============================================================================
// Kernel 3: row softmax. grid B*NH*S blocks of 256.
// ============================================================================
__global__ __launch_bounds__(256) void softmax_kernel(float* __restrict__ attn)
{
    float* p = attn + (size_t)blockIdx.x * S_;
    const int t = threadIdx.x;
    float4 v0 = ((float4*)p)[t];
    float4 v1 = ((float4*)p)[t + 256];
    float m = fmaxf(fmaxf(fmaxf(v0.x, v0.y), fmaxf(v0.z, v0.w)),
                    fmaxf(fmaxf(v1.x, v1.y), fmaxf(v1.z, v1.w)));
    __shared__ float red[256];
    red[t] = m;
    __syncthreads();
#pragma unroll
    for (int s = 128; s > 0; s >>= 1) {
        if (t < s) red[t] = fmaxf(red[t], red[t + s]);
        __syncthreads();
    }
    m = red[0];
    __syncthreads();
    v0.x = __expf(v0.x - m); v0.y = __expf(v0.y - m);
    v0.z = __expf(v0.z - m); v0.w = __expf(v0.w - m);
    v1.x = __expf(v1.x - m); v1.y = __expf(v1.y - m);
    v1.z = __expf(v1.z - m); v1.w = __expf(v1.w - m);
    float s8 = (v0.x + v0.y + v0.z + v0.w) + (v1.x + v1.y + v1.z + v1.w);
    red[t] = s8;
    __syncthreads();
#pragma unroll
    for (int s = 128; s > 0; s >>= 1) {
        if (t < s) red[t] += red[t + s];
        __syncthreads();
    }
    const float inv = 1.f / red[0];
    v0.x *= inv; v0.y *= inv; v0.z *= inv; v0.w *= inv;
    v1.x *= inv; v1.y *= inv; v1.z *= inv; v1.w *= inv;
    ((float4*)p)[t]       = v0;
    ((float4*)p)[t + 256] = v1;
}

// ============================================================================
// Kernel 4: ctx = attn @ v. grid (S/128, B*NH). BN=64, K=2048, 32 buffers.
// Warp grid 4x2, warp tile 32x32 (MT=2).
// ============================================================================
__global__ __launch_bounds__(256, 1) void ctx_mma(const float* __restrict__ attn)
{
    extern __shared__ char smem[];
    const int z = blockIdx.y, b = z >> 4, nh = z & 15;
    const int tid = threadIdx.x, wid = tid >> 5, lane = tid & 31;
    const int m0 = blockIdx.x * 128;
    const int wmr = (wid & 3) * 32, wnc = (wid >> 2) * 32;
    const uint32_t sb = smem_u32(smem);
    const float* Az = attn + (size_t)z * S_ * S_ + (size_t)m0 * S_;
    const float* vb = g_v + (size_t)b * S_ * H_ + nh * D_;
    float* cb = g_ctx + (size_t)b * S_ * H_ + nh * D_;

    float acc[2][4][4];
#pragma unroll
    for (int a = 0; a < 2; a++)
#pragma unroll
        for (int c = 0; c < 4; c++)
#pragma unroll
            for (int d = 0; d < 4; d++) acc[a][c][d] = 0.f;

    float4 pa[8];
    float  pb[16];
    ldg_kcontig(Az, S_, tid, pa);
    ldg_kstrided<64>(vb, H_, tid, pb);
    sts_kcontig(pa, smem, tid, T_AHI(0), T_ALO(0));
    sts_kstrided<64>(pb, smem, tid, T_BHI(0), T_BLO(0));
    __syncthreads();

    const int NIT = S_ / 64;
    for (int it = 0; it < NIT; it++) {
        const int cur = it & 1, nxt = cur ^ 1;
        if (it + 1 < NIT) {
            ldg_kcontig(Az + (it + 1) * 64, S_, tid, pa);
            ldg_kstrided<64>(vb + (size_t)(it + 1) * 64 * H_, H_, tid, pb);
        }
        compute_buf<2>(sb + T_AHI(cur), sb + T_ALO(cur),
                       sb + T_BHI(cur), sb + T_BLO(cur), wmr, wnc, lane, acc);
        if (it + 1 < NIT) {
            sts_kcontig(pa, smem, tid, T_AHI(nxt), T_ALO(nxt));
            sts_kstrided<64>(pb, smem, tid, T_BHI(nxt), T_BLO(nxt));
        }
        __syncthreads();
    }
    store_acc<2>(cb + (size_t)m0 * H_, H_, 1.f, wmr, wnc, lane, acc);
}

// ============================================================================
// Kernel 5: out = ctx @ Wo. grid (H/128, MBS/128). K=1024, 16 buffers.
// ============================================================================
__global__ __launch_bounds__(256, 1) void outproj_mma(
    const float* __restrict__ Wo, float* __restrict__ out)
{
    extern __shared__ char smem[];
    const int tid = threadIdx.x, wid = tid >> 5, lane = tid & 31;
    const int m0 = blockIdx.y * 128, n0 = blockIdx.x * 128;
    const int wmr = (wid & 1) * 64, wnc = (wid >> 1) * 32;
    const uint32_t sb = smem_u32(smem);

    float acc[4][4][4];
#pragma unroll
    for (int a = 0; a < 4; a++)
#pragma unroll
        for (int c = 0; c < 4; c++)
#pragma unroll
            for (int d = 0; d < 4; d++) acc[a][c][d] = 0.f;

    float4 pa[8];
    float  pb[32];
    ldg_kcontig(g_ctx + (size_t)m0 * H_, H_, tid, pa);
    ldg_kstrided<128>(Wo + n0, H_, tid, pb);
    sts_kcontig(pa, smem, tid, T_AHI(0), T_ALO(0));
    sts_kstrided<128>(pb, smem, tid, T_BHI(0), T_BLO(0));
    __syncthreads();

    const int NIT = H_ / 64;
    for (int it = 0; it < NIT; it++) {
        const int cur = it & 1, nxt = cur ^ 1;
        if (it + 1 < NIT) {
            ldg_kcontig(g_ctx + (size_t)m0 * H_ + (it + 1) * 64, H_, tid, pa);
            ldg_kstrided<128>(Wo + (size_t)(it + 1) * 64 * H_ + n0, H_, tid, pb);
        }
        compute_buf<4>(sb + T_AHI(cur), sb + T_ALO(cur),
                       sb + T_BHI(cur), sb + T_BLO(cur), wmr, wnc, lane, acc);
        if (it + 1 < NIT) {
            sts_kcontig(pa, smem, tid, T_AHI(nxt), T_ALO(nxt));
            sts_kstrided<128>(pb, smem, tid, T_BHI(nxt), T_BLO(nxt));
        }
        __syncthreads();
    }
    store_acc<4>(out + (size_t)m0 * H_ + n0, H_, 1.f, wmr, wnc, lane, acc);
}

// ============================================================================
extern "C" void kernel_launch(void* const* d_in, const int* in_sizes, int n_in,
                              void* d_out, int out_size)
{
    const float* q  = (const float*)d_in[0];
    const float* k  = (const float*)d_in[1];
    const float* v  = (const float*)d_in[2];
    const float* Wq = (const float*)d_in[3];
    const float* Wk = (const float*)d_in[4];
    const float* Wv = (const float*)d_in[5];
    const float* Wo = (const float*)d_in[6];
    float* out = (float*)d_out;

    const bool attn_in_out = ((size_t)out_size >= OUT_ELEMS + ATTN_ELEMS);
    float* attn;
    if (attn_in_out) {
        attn = out + OUT_ELEMS;
    } else {
        void* p = nullptr;
        cudaGetSymbolAddress(&p, g_attn_fallback);
        attn = (float*)p;
    }

    cudaFuncSetAttribute(proj_mma,    cudaFuncAttributeMaxDynamicSharedMemorySize, SMEM_BYTES);
    cudaFuncSetAttribute(scores_mma,  cudaFuncAttributeMaxDynamicSharedMemorySize, SMEM_BYTES);
    cudaFuncSetAttribute(ctx_mma,     cudaFuncAttributeMaxDynamicSharedMemorySize, SMEM_BYTES);
    cudaFuncSetAttribute(outproj_mma, cudaFuncAttributeMaxDynamicSharedMemorySize, SMEM_BYTES);

    {
        dim3 g(H_ / 128, MBS / 128, 3);
        proj_mma<<<g, 256, SMEM_BYTES>>>(q, k, v, Wq, Wk, Wv);
    }
    {
        dim3 g(S_ / 128, S_ / 128, B_ * NH_);
        scores_mma<<<g, 256, SMEM_BYTES>>>(attn);
    }
    softmax_kernel<<<B_ * NH_ * S_, 256>>>(attn);
    {
        dim3 g(S_ / 128, B_ * NH_);
        ctx_mma<<<g, 256, SMEM_BYTES>>>(attn);
    }
    {
        dim3 g(H_ / 128, MBS / 128);
        outproj_mma<<<g, 256, SMEM_BYTES>>>(Wo, out);
    }
}

// round 7
// speedup vs baseline: 1.5104x; 1.5104x over previous
#include <cuda_runtime.h>
#include <cuda_bf16.h>
#include <cstdint>

#define B_   2
#define S_   2048
#define H_   1024
#define NH_  16
#define D_   64
#define MBS  (B_ * S_)

#define OUT_ELEMS  ((size_t)B_ * S_ * H_)
#define ATTN_ELEMS ((size_t)B_ * NH_ * S_ * S_)

// Scratch (device globals — no allocations allowed).
__device__ float g_q[OUT_ELEMS];
__device__ float g_k[OUT_ELEMS];
__device__ float g_v[OUT_ELEMS];
__device__ float g_ctx[OUT_ELEMS];
__device__ float g_attn_fallback[ATTN_ELEMS];

#define SMEM_SWIZZLE_128B(b) ((b) ^ (((b) >> 3) & 0x70))

// Smem: 2 buffers x (Ahi, Alo, Bhi, Blo) tiles of 16KB (128 rows x 128B).
#define T_AHI(buf) ((buf) * 65536 + 0)
#define T_ALO(buf) ((buf) * 65536 + 16384)
#define T_BHI(buf) ((buf) * 65536 + 32768)
#define T_BLO(buf) ((buf) * 65536 + 49152)
#define SMEM_BYTES 131072

__device__ __forceinline__ uint32_t smem_u32(const void* p) {
    uint32_t a;
    asm("{ .reg .u64 t; cvta.to.shared.u64 t, %1; cvt.u32.u64 %0, t; }"
        : "=r"(a) : "l"(p));
    return a;
}

__device__ __forceinline__ void ldsm_x4(uint32_t addr, uint32_t r[4]) {
    asm volatile("ldmatrix.sync.aligned.m8n8.x4.shared.b16 {%0,%1,%2,%3}, [%4];"
                 : "=r"(r[0]), "=r"(r[1]), "=r"(r[2]), "=r"(r[3]) : "r"(addr));
}

__device__ __forceinline__ void mma16816(float d[4], const uint32_t a[4],
                                         const uint32_t b[2]) {
    asm volatile(
        "mma.sync.aligned.m16n8k16.row.col.f32.bf16.bf16.f32 "
        "{%0,%1,%2,%3}, {%4,%5,%6,%7}, {%8,%9}, {%0,%1,%2,%3};"
        : "+f"(d[0]), "+f"(d[1]), "+f"(d[2]), "+f"(d[3])
        : "r"(a[0]), "r"(a[1]), "r"(a[2]), "r"(a[3]), "r"(b[0]), "r"(b[1]));
}

// f32 pair -> packed bf16x2 hi + bf16x2 lo (3-term split precision)
__device__ __forceinline__ void cv_pair(float x0, float x1,
                                        uint32_t& ph, uint32_t& pl) {
    __nv_bfloat16 h0 = __float2bfloat16(x0);
    __nv_bfloat16 h1 = __float2bfloat16(x1);
    __nv_bfloat16 l0 = __float2bfloat16(x0 - __bfloat162float(h0));
    __nv_bfloat16 l1 = __float2bfloat16(x1 - __bfloat162float(h1));
    ph = (uint32_t)__bfloat16_as_ushort(h0) | ((uint32_t)__bfloat16_as_ushort(h1) << 16);
    pl = (uint32_t)__bfloat16_as_ushort(l0) | ((uint32_t)__bfloat16_as_ushort(l1) << 16);
}

// ---------------------------------------------------------------------------
// Loaders: LDG (prefetch to regs) + STS (convert + store) halves.
// Tile layout: smem row = output row index (m or n), 64 bf16 k = 128B rows,
// swizzled by SMEM_SWIZZLE_128B.
// ---------------------------------------------------------------------------
__device__ __forceinline__ void ldg_kcontig(const float* __restrict__ base,
                                            size_t ld, int tid, float4 pa[8]) {
    const int row = tid >> 1, kb = (tid & 1) * 32;
    const float* src = base + (size_t)row * ld + kb;
#pragma unroll
    for (int j = 0; j < 8; j++) pa[j] = *(const float4*)(src + j * 4);
}

// FIXED (R5 NaN bug): per-j stride is 8 bytes (4 bf16 k-values -> h0 @ +0,
// h1 @ +4), previously j*16 which skipped bytes and overran the tile.
__device__ __forceinline__ void sts_kcontig(const float4 pa[8], char* smem,
                                            int tid, int hi, int lo) {
    const int row = tid >> 1, kb = (tid & 1) * 32;
    char* shi = smem + hi;
    char* slo = smem + lo;
#pragma unroll
    for (int j = 0; j < 8; j++) {
        uint32_t h0, l0, h1, l1;
        cv_pair(pa[j].x, pa[j].y, h0, l0);
        cv_pair(pa[j].z, pa[j].w, h1, l1);
        uint32_t b0 = SMEM_SWIZZLE_128B(row * 128 + kb * 2 + j * 8);
        *(uint32_t*)(shi + b0)     = h0;
        *(uint32_t*)(shi + b0 + 4) = h1;
        *(uint32_t*)(slo + b0)     = l0;
        *(uint32_t*)(slo + b0 + 4) = l1;
    }
}

// proj W: B tile row c (output col), content k=h: W[(c>>6)*H*D + h*64 + (c&63)]
__device__ __forceinline__ void ldg_projW(const float* __restrict__ W,
                                          int n0, int k0, int tid, float pb[32]) {
#pragma unroll
    for (int j = 0; j < 16; j++) {
        int idx = j * 256 + tid;
        int n   = idx & 127;
        int kk  = (idx >> 7) * 2;
        int ng  = n0 + n;
        const float* src = W + ((size_t)(ng >> 6) << 16)
                             + (size_t)(k0 + kk) * 64 + (ng & 63);
        pb[2 * j]     = src[0];
        pb[2 * j + 1] = src[64];
    }
}

__device__ __forceinline__ void sts_projW(const float pb[32], char* smem,
                                          int tid, int hi, int lo) {
    char* shi = smem + hi;
    char* slo = smem + lo;
#pragma unroll
    for (int j = 0; j < 16; j++) {
        int idx = j * 256 + tid;
        int n   = idx & 127;
        int kk  = (idx >> 7) * 2;
        uint32_t h, l;
        cv_pair(pb[2 * j], pb[2 * j + 1], h, l);
        uint32_t b = SMEM_SWIZZLE_128B(n * 128 + kk * 2);
        *(uint32_t*)(shi + b) = h;
        *(uint32_t*)(slo + b) = l;
    }
}

// K-strided B: element (n, k) = base[k*strideK + n], NR rows.
template <int NR>
__device__ __forceinline__ void ldg_kstrided(const float* __restrict__ base,
                                             size_t sK, int tid, float pb[]) {
#pragma unroll
    for (int j = 0; j < NR / 8; j++) {
        int idx = j * 256 + tid;
        int n   = idx & (NR - 1);
        int kk  = (idx / NR) * 2;
        pb[2 * j]     = base[(size_t)kk * sK + n];
        pb[2 * j + 1] = base[(size_t)(kk + 1) * sK + n];
    }
}

template <int NR>
__device__ __forceinline__ void sts_kstrided(const float pb[], char* smem,
                                             int tid, int hi, int lo) {
    char* shi = smem + hi;
    char* slo = smem + lo;
#pragma unroll
    for (int j = 0; j < NR / 8; j++) {
        int idx = j * 256 + tid;
        int n   = idx & (NR - 1);
        int kk  = (idx / NR) * 2;
        uint32_t h, l;
        cv_pair(pb[2 * j], pb[2 * j + 1], h, l);
        uint32_t b = SMEM_SWIZZLE_128B(n * 128 + kk * 2);
        *(uint32_t*)(shi + b) = h;
        *(uint32_t*)(slo + b) = l;
    }
}

// ---------------------------------------------------------------------------
// Warp-MMA compute over one BK=64 buffer. Warp tile = MT m16-tiles x 4 n8-tiles.
// 3-term bf16 split: hh + hl + lh into fp32 acc.
// ---------------------------------------------------------------------------
template <int MT>
__device__ __forceinline__ void compute_buf(uint32_t sAhi, uint32_t sAlo,
                                            uint32_t sBhi, uint32_t sBlo,
                                            int wmr, int wnc, int lane,
                                            float (&acc)[MT][4][4]) {
    const int j = lane >> 3, r = lane & 7;
    const int arow = ((j & 1) << 3) + r, aoff = (j >> 1) << 4;
    const int brow = ((j >> 1) << 3) + r, boff = (j & 1) << 4;
    const int xr = r << 4;
#pragma unroll
    for (int kk = 0; kk < 4; kk++) {
        uint32_t ah[MT][4], al[MT][4];
#pragma unroll
        for (int mt = 0; mt < MT; mt++) {
            uint32_t off = (uint32_t)((wmr + mt * 16 + arow) * 128
                                      + (((kk << 5) + aoff) ^ xr));
            ldsm_x4(sAhi + off, ah[mt]);
            ldsm_x4(sAlo + off, al[mt]);
        }
        uint32_t bh[2][4], bl[2][4];
#pragma unroll
        for (int g = 0; g < 2; g++) {
            uint32_t off = (uint32_t)((wnc + g * 16 + brow) * 128
                                      + (((kk << 5) + boff) ^ xr));
            ldsm_x4(sBhi + off, bh[g]);
            ldsm_x4(sBlo + off, bl[g]);
        }
#pragma unroll
        for (int mt = 0; mt < MT; mt++)
#pragma unroll
            for (int nt = 0; nt < 4; nt++) {
                const uint32_t* bhp = &bh[nt >> 1][(nt & 1) * 2];
                const uint32_t* blp = &bl[nt >> 1][(nt & 1) * 2];
                mma16816(acc[mt][nt], ah[mt], bhp);
                mma16816(acc[mt][nt], ah[mt], blp);
                mma16816(acc[mt][nt], al[mt], bhp);
            }
    }
}

template <int MT>
__device__ __forceinline__ void store_acc(float* C, size_t ldc, float scale,
                                          int wmr, int wnc, int lane,
                                          const float (&acc)[MT][4][4]) {
    const int rr = lane >> 2, cc = (lane & 3) * 2;
#pragma unroll
    for (int mt = 0; mt < MT; mt++)
#pragma unroll
        for (int nt = 0; nt < 4; nt++) {
            float* p0 = C + (size_t)(wmr + mt * 16 + rr) * ldc + wnc + nt * 8 + cc;
            *(float2*)p0 = make_float2(acc[mt][nt][0] * scale,
                                       acc[mt][nt][1] * scale);
            *(float2*)(p0 + 8 * ldc) = make_float2(acc[mt][nt][2] * scale,
                                                   acc[mt][nt][3] * scale);
        }
}

// ============================================================================
// Kernel 1: q/k/v projections. grid (H/128, MBS/128, 3). K=1024, 16 buffers.
// ============================================================================
__global__ __launch_bounds__(256, 1) void proj_mma(
    const float* __restrict__ inq, const float* __restrict__ ink,
    const float* __restrict__ inv,
    const float* __restrict__ Wq, const float* __restrict__ Wk,
    const float* __restrict__ Wv)
{
    extern __shared__ char smem[];
    const int z = blockIdx.z;
    const float* A = (z == 0) ? inq : (z == 1) ? ink : inv;
    const float* W = (z == 0) ? Wq  : (z == 1) ? Wk  : Wv;
    float* C       = (z == 0) ? g_q : (z == 1) ? g_k : g_v;

    const int tid = threadIdx.x, wid = tid >> 5, lane = tid & 31;
    const int m0 = blockIdx.y * 128, n0 = blockIdx.x * 128;
    const int wmr = (wid & 1) * 64, wnc = (wid >> 1) * 32;
    const uint32_t sb = smem_u32(smem);

    float acc[4][4][4];
#pragma unroll
    for (int a = 0; a < 4; a++)
#pragma unroll
        for (int b = 0; b < 4; b++)
#pragma unroll
            for (int c = 0; c < 4; c++) acc[a][b][c] = 0.f;

    float4 pa[8];
    float  pb[32];
    ldg_kcontig(A + (size_t)m0 * H_, H_, tid, pa);
    ldg_projW(W, n0, 0, tid, pb);
    sts_kcontig(pa, smem, tid, T_AHI(0), T_ALO(0));
    sts_projW(pb, smem, tid, T_BHI(0), T_BLO(0));
    __syncthreads();

    const int NIT = H_ / 64;
    for (int it = 0; it < NIT; it++) {
        const int cur = it & 1, nxt = cur ^ 1;
        if (it + 1 < NIT) {
            ldg_kcontig(A + (size_t)m0 * H_ + (it + 1) * 64, H_, tid, pa);
            ldg_projW(W, n0, (it + 1) * 64, tid, pb);
        }
        compute_buf<4>(sb + T_AHI(cur), sb + T_ALO(cur),
                       sb + T_BHI(cur), sb + T_BLO(cur), wmr, wnc, lane, acc);
        if (it + 1 < NIT) {
            sts_kcontig(pa, smem, tid, T_AHI(nxt), T_ALO(nxt));
            sts_projW(pb, smem, tid, T_BHI(nxt), T_BLO(nxt));
        }
        __syncthreads();
    }
    store_acc<4>(C + (size_t)m0 * H_ + n0, H_, 1.f, wmr, wnc, lane, acc);
}

// ============================================================================
// Kernel 2: scores = q k^T / 8. grid (S/128, S/128, B*NH). K=64, one buffer.
// ============================================================================
__global__ __launch_bounds__(256, 1) void scores_mma(float* __restrict__ attn)
{
    extern __shared__ char smem[];
    const int z = blockIdx.z, b = z >> 4, n = z & 15;
    const int tid = threadIdx.x, wid = tid >> 5, lane = tid & 31;
    const int m0 = blockIdx.y * 128, n0 = blockIdx.x * 128;
    const int wmr = (wid & 1) * 64, wnc = (wid >> 1) * 32;
    const uint32_t sb = smem_u32(smem);
    const float* qb = g_q + (size_t)b * S_ * H_ + n * D_;
    const float* kb = g_k + (size_t)b * S_ * H_ + n * D_;

    float acc[4][4][4];
#pragma unroll
    for (int a = 0; a < 4; a++)
#pragma unroll
        for (int c = 0; c < 4; c++)
#pragma unroll
            for (int d = 0; d < 4; d++) acc[a][c][d] = 0.f;

    float4 pa[8];
    ldg_kcontig(qb + (size_t)m0 * H_, H_, tid, pa);
    sts_kcontig(pa, smem, tid, T_AHI(0), T_ALO(0));
    ldg_kcontig(kb + (size_t)n0 * H_, H_, tid, pa);
    sts_kcontig(pa, smem, tid, T_BHI(0), T_BLO(0));
    __syncthreads();

    compute_buf<4>(sb + T_AHI(0), sb + T_ALO(0),
                   sb + T_BHI(0), sb + T_BLO(0), wmr, wnc, lane, acc);

    store_acc<4>(attn + (size_t)z * S_ * S_ + (size_t)m0 * S_ + n0,
                 S_, 0.125f, wmr, wnc, lane, acc);
}

// ============================================================================
// Kernel 3: row softmax. grid B*NH*S blocks of 256.
// ============================================================================
__global__ __launch_bounds__(256) void softmax_kernel(float* __restrict__ attn)
{
    float* p = attn + (size_t)blockIdx.x * S_;
    const int t = threadIdx.x;
    float4 v0 = ((float4*)p)[t];
    float4 v1 = ((float4*)p)[t + 256];
    float m = fmaxf(fmaxf(fmaxf(v0.x, v0.y), fmaxf(v0.z, v0.w)),
                    fmaxf(fmaxf(v1.x, v1.y), fmaxf(v1.z, v1.w)));
    __shared__ float red[256];
    red[t] = m;
    __syncthreads();
#pragma unroll
    for (int s = 128; s > 0; s >>= 1) {
        if (t < s) red[t] = fmaxf(red[t], red[t + s]);
        __syncthreads();
    }
    m = red[0];
    __syncthreads();
    v0.x = __expf(v0.x - m); v0.y = __expf(v0.y - m);
    v0.z = __expf(v0.z - m); v0.w = __expf(v0.w - m);
    v1.x = __expf(v1.x - m); v1.y = __expf(v1.y - m);
    v1.z = __expf(v1.z - m); v1.w = __expf(v1.w - m);
    float s8 = (v0.x + v0.y + v0.z + v0.w) + (v1.x + v1.y + v1.z + v1.w);
    red[t] = s8;
    __syncthreads();
#pragma unroll
    for (int s = 128; s > 0; s >>= 1) {
        if (t < s) red[t] += red[t + s];
        __syncthreads();
    }
    const float inv = 1.f / red[0];
    v0.x *= inv; v0.y *= inv; v0.z *= inv; v0.w *= inv;
    v1.x *= inv; v1.y *= inv; v1.z *= inv; v1.w *= inv;
    ((float4*)p)[t]       = v0;
    ((float4*)p)[t + 256] = v1;
}

// ============================================================================
// Kernel 4: ctx = attn @ v. grid (S/128, B*NH). BN=64, K=2048, 32 buffers.
// Warp grid 4x2, warp tile 32x32 (MT=2).
// ============================================================================
__global__ __launch_bounds__(256, 1) void ctx_mma(const float* __restrict__ attn)
{
    extern __shared__ char smem[];
    const int z = blockIdx.y, b = z >> 4, nh = z & 15;
    const int tid = threadIdx.x, wid = tid >> 5, lane = tid & 31;
    const int m0 = blockIdx.x * 128;
    const int wmr = (wid & 3) * 32, wnc = (wid >> 2) * 32;
    const uint32_t sb = smem_u32(smem);
    const float* Az = attn + (size_t)z * S_ * S_ + (size_t)m0 * S_;
    const float* vb = g_v + (size_t)b * S_ * H_ + nh * D_;
    float* cb = g_ctx + (size_t)b * S_ * H_ + nh * D_;

    float acc[2][4][4];
#pragma unroll
    for (int a = 0; a < 2; a++)
#pragma unroll
        for (int c = 0; c < 4; c++)
#pragma unroll
            for (int d = 0; d < 4; d++) acc[a][c][d] = 0.f;

    float4 pa[8];
    float  pb[16];
    ldg_kcontig(Az, S_, tid, pa);
    ldg_kstrided<64>(vb, H_, tid, pb);
    sts_kcontig(pa, smem, tid, T_AHI(0), T_ALO(0));
    sts_kstrided<64>(pb, smem, tid, T_BHI(0), T_BLO(0));
    __syncthreads();

    const int NIT = S_ / 64;
    for (int it = 0; it < NIT; it++) {
        const int cur = it & 1, nxt = cur ^ 1;
        if (it + 1 < NIT) {
            ldg_kcontig(Az + (it + 1) * 64, S_, tid, pa);
            ldg_kstrided<64>(vb + (size_t)(it + 1) * 64 * H_, H_, tid, pb);
        }
        compute_buf<2>(sb + T_AHI(cur), sb + T_ALO(cur),
                       sb + T_BHI(cur), sb + T_BLO(cur), wmr, wnc, lane, acc);
        if (it + 1 < NIT) {
            sts_kcontig(pa, smem, tid, T_AHI(nxt), T_ALO(nxt));
            sts_kstrided<64>(pb, smem, tid, T_BHI(nxt), T_BLO(nxt));
        }
        __syncthreads();
    }
    store_acc<2>(cb + (size_t)m0 * H_, H_, 1.f, wmr, wnc, lane, acc);
}

// ============================================================================
// Kernel 5: out = ctx @ Wo. grid (H/128, MBS/128). K=1024, 16 buffers.
// ============================================================================
__global__ __launch_bounds__(256, 1) void outproj_mma(
    const float* __restrict__ Wo, float* __restrict__ out)
{
    extern __shared__ char smem[];
    const int tid = threadIdx.x, wid = tid >> 5, lane = tid & 31;
    const int m0 = blockIdx.y * 128, n0 = blockIdx.x * 128;
    const int wmr = (wid & 1) * 64, wnc = (wid >> 1) * 32;
    const uint32_t sb = smem_u32(smem);

    float acc[4][4][4];
#pragma unroll
    for (int a = 0; a < 4; a++)
#pragma unroll
        for (int c = 0; c < 4; c++)
#pragma unroll
            for (int d = 0; d < 4; d++) acc[a][c][d] = 0.f;

    float4 pa[8];
    float  pb[32];
    ldg_kcontig(g_ctx + (size_t)m0 * H_, H_, tid, pa);
    ldg_kstrided<128>(Wo + n0, H_, tid, pb);
    sts_kcontig(pa, smem, tid, T_AHI(0), T_ALO(0));
    sts_kstrided<128>(pb, smem, tid, T_BHI(0), T_BLO(0));
    __syncthreads();

    const int NIT = H_ / 64;
    for (int it = 0; it < NIT; it++) {
        const int cur = it & 1, nxt = cur ^ 1;
        if (it + 1 < NIT) {
            ldg_kcontig(g_ctx + (size_t)m0 * H_ + (it + 1) * 64, H_, tid, pa);
            ldg_kstrided<128>(Wo + (size_t)(it + 1) * 64 * H_ + n0, H_, tid, pb);
        }
        compute_buf<4>(sb + T_AHI(cur), sb + T_ALO(cur),
                       sb + T_BHI(cur), sb + T_BLO(cur), wmr, wnc, lane, acc);
        if (it + 1 < NIT) {
            sts_kcontig(pa, smem, tid, T_AHI(nxt), T_ALO(nxt));
            sts_kstrided<128>(pb, smem, tid, T_BHI(nxt), T_BLO(nxt));
        }
        __syncthreads();
    }
    store_acc<4>(out + (size_t)m0 * H_ + n0, H_, 1.f, wmr, wnc, lane, acc);
}

// ============================================================================
extern "C" void kernel_launch(void* const* d_in, const int* in_sizes, int n_in,
                              void* d_out, int out_size)
{
    const float* q  = (const float*)d_in[0];
    const float* k  = (const float*)d_in[1];
    const float* v  = (const float*)d_in[2];
    const float* Wq = (const float*)d_in[3];
    const float* Wk = (const float*)d_in[4];
    const float* Wv = (const float*)d_in[5];
    const float* Wo = (const float*)d_in[6];
    float* out = (float*)d_out;

    const bool attn_in_out = ((size_t)out_size >= OUT_ELEMS + ATTN_ELEMS);
    float* attn;
    if (attn_in_out) {
        attn = out + OUT_ELEMS;
    } else {
        void* p = nullptr;
        cudaGetSymbolAddress(&p, g_attn_fallback);
        attn = (float*)p;
    }

    cudaFuncSetAttribute(proj_mma,    cudaFuncAttributeMaxDynamicSharedMemorySize, SMEM_BYTES);
    cudaFuncSetAttribute(scores_mma,  cudaFuncAttributeMaxDynamicSharedMemorySize, SMEM_BYTES);
    cudaFuncSetAttribute(ctx_mma,     cudaFuncAttributeMaxDynamicSharedMemorySize, SMEM_BYTES);
    cudaFuncSetAttribute(outproj_mma, cudaFuncAttributeMaxDynamicSharedMemorySize, SMEM_BYTES);

    {
        dim3 g(H_ / 128, MBS / 128, 3);
        proj_mma<<<g, 256, SMEM_BYTES>>>(q, k, v, Wq, Wk, Wv);
    }
    {
        dim3 g(S_ / 128, S_ / 128, B_ * NH_);
        scores_mma<<<g, 256, SMEM_BYTES>>>(attn);
    }
    softmax_kernel<<<B_ * NH_ * S_, 256>>>(attn);
    {
        dim3 g(S_ / 128, B_ * NH_);
        ctx_mma<<<g, 256, SMEM_BYTES>>>(attn);
    }
    {
        dim3 g(H_ / 128, MBS / 128);
        outproj_mma<<<g, 256, SMEM_BYTES>>>(Wo, out);
    }
}